// round 15
// baseline (speedup 1.0000x reference)
#include <cuda_runtime.h>
#include <cstdint>

#define HR 158
#define HO 156
#define WO 156
#define CH_STRIDE (158*160)

// smem: band tile only
#define SMEM_TOTAL (21*80*4)   // 6720 B

// At frag-ordered: [b][y 158][p 2] x [mt 5][ks 16][lane 32][4]  (10240 f/pane)
__device__ __align__(16) float g_At[(size_t)4*158*2*10240];
// Bt frag-ordered: [b][y2i 198][p 2] x [kh 2][T 13][ks2 4][lane 32][4] (13312 f/pane)
__device__ __align__(16) float g_Bt[(size_t)4*198*2*13312];
// raw, parity-split rows: [b*441+ch][y 158][p 2][m 80]  (~178 MB)
__device__ __align__(16) float g_raw[(size_t)4*441*158*160];

static __device__ __forceinline__ float to_tf32(float x){
    float r; asm("cvt.rna.tf32.f32 %0, %1;" : "=f"(r) : "f"(x)); return r;
}

// ---------------- Pass 0: fused transpose/pad into FRAGMENT-ORDER tiles ------
// grid.x: [0,158) -> A row y ; [158,356) -> B row y2i. grid.y = b.
__global__ __launch_bounds__(256) void transAB(const float* __restrict__ in1,
                                               const float* __restrict__ in2){
    __shared__ float sm[32*193];
    const int bx = blockIdx.x, b = blockIdx.y;
    const int tid = threadIdx.x;

    if (bx < 158){
        const int y = bx;
        float* outp = g_At + (size_t)((b*158 + y)*2) * 10240;
        for (int cc = 0; cc < 4; ++cc){
            const int c0 = cc*32;
            __syncthreads();
            for (int idx = tid; idx < 32*192; idx += 256){
                int cl = idx / 192, xx = idx - cl*192;
                sm[cl*193 + xx] = in1[(((size_t)b*128 + c0 + cl)*192 + (y+17))*192 + xx];
            }
            __syncthreads();
            // 1280 float4 frag words: v -> (pp, mt, ks_l, lane)
            #pragma unroll
            for (int it = 0; it < 5; ++it){
                int v = tid + it*256;
                int lane = v & 31;
                int q = v >> 5;            // 0..39
                int ks_l = q & 3; q >>= 2; // 0..9
                int mt = q % 5, pp = q / 5;
                int grp = lane >> 2, tig = lane & 3;
                int m = 16*mt + grp;
                int x = 2*m + pp + 17;
                int cl = ks_l*8 + tig;
                float4 o;
                o.x = to_tf32(sm[cl*193 + x]);
                o.z = to_tf32(sm[(cl+4)*193 + x]);
                if (m + 8 <= 78){
                    o.y = to_tf32(sm[cl*193 + x + 16]);
                    o.w = to_tf32(sm[(cl+4)*193 + x + 16]);
                } else { o.y = 0.f; o.w = 0.f; }
                int ks = cc*4 + ks_l;
                float* dst = outp + (size_t)pp*10240 + ((mt*16 + ks)*32 + lane)*4;
                *reinterpret_cast<float4*>(dst) = o;
            }
        }
    } else {
        const int y2i = bx - 158;
        const int y2 = y2i - 3;
        const bool rowok = (y2 >= 0 && y2 < 192);
        float* outp = g_Bt + (size_t)((b*198 + y2i)*2) * 13312;
        for (int cc = 0; cc < 4; ++cc){
            const int c0 = cc*32;
            __syncthreads();
            for (int idx = tid; idx < 32*192; idx += 256){
                int cl = idx / 192, xx = idx - cl*192;
                sm[cl*193 + xx] = rowok ?
                    in2[(((size_t)b*128 + c0 + cl)*192 + y2)*192 + xx] : 0.f;
            }
            __syncthreads();
            // 3328 float2 frag words: v -> (pp, T, ks_l, lane)
            const int kh = cc >> 1, kslc = (cc & 1)*4;
            #pragma unroll
            for (int it = 0; it < 13; ++it){
                int v = tid + it*256;
                int lane = v & 31;
                int q = v >> 5;            // 0..103
                int ks_l = q & 3; q >>= 2; // 0..25
                int T = q % 13, pp = q / 13;
                int grp = lane >> 2, tig = lane & 3;
                int n = T*8 + grp;
                int x = 2*n + pp - 3;
                int cl = ks_l*8 + tig;
                float2 o;
                o.x = ((unsigned)x < 192u) ? to_tf32(sm[cl*193 + x]) : 0.f;
                o.y = ((unsigned)x < 192u) ? to_tf32(sm[(cl+4)*193 + x]) : 0.f;
                int ksl = kslc + ks_l;
                // [kh][T][ks2][lane][4]: words 0-1 = ksl even, 2-3 = ksl odd
                float* dst = outp + (size_t)pp*13312 +
                             ((((kh*13 + T)*4 + (ksl >> 1))*32 + lane)*4 + (ksl & 1)*2);
                *reinterpret_cast<float2*>(dst) = o;
            }
        }
    }
}

// ---------------- helpers ----------------
__device__ __forceinline__ void mma8(float* d, const uint32_t* a, uint32_t b0, uint32_t b1){
    asm volatile(
        "mma.sync.aligned.m16n8k8.row.col.f32.tf32.tf32.f32 "
        "{%0,%1,%2,%3}, {%4,%5,%6,%7}, {%8,%9}, {%0,%1,%2,%3};"
        : "+f"(d[0]), "+f"(d[1]), "+f"(d[2]), "+f"(d[3])
        : "r"(a[0]), "r"(a[1]), "r"(a[2]), "r"(a[3]), "r"(b0), "r"(b1));
}

// ---------------- Pass 1: banded tf32 MMA, both operands via LDG ------------
// grid (y 158, p 2, b 4); block 160 = 5 warps, warp w owns m-rows 16w..16w+15
// and n8-tiles T = 2w..2w+4. No smem staging for A or B.
extern __shared__ __align__(16) char smem_dyn[];

__global__ __launch_bounds__(160, 3)
void corr_mma(){
    const int y = blockIdx.x, p = blockIdx.y, b = blockIdx.z;
    const int tid = threadIdx.x, w = tid >> 5, lane = tid & 31;
    const int grp = lane >> 2, tig = lane & 3;
    float* Dsm = (float*)smem_dyn;

    const float* Ap = g_At + ((size_t)(b*158 + y)*2 + p) * 10240;
    const size_t bbase = ((size_t)b*198 + y)*2 + p;
    const int m0 = 16*w + grp;

    // A fragments: 16 coalesced LDG.128 per thread, once per block
    uint32_t areg[64];
    {
        const uint4* Af = (const uint4*)Ap;
        #pragma unroll
        for (int ks = 0; ks < 16; ++ks){
            uint4 f = __ldg(&Af[(w*16 + ks)*32 + lane]);
            areg[ks*4+0] = f.x; areg[ks*4+1] = f.y;
            areg[ks*4+2] = f.z; areg[ks*4+3] = f.w;
        }
    }

    for (int pane = 0; pane <= 20; ++pane){
        const uint4* Bf = (const uint4*)(g_Bt + (bbase + (size_t)pane*4) * 13312);

        float dacc[5][4];
        #pragma unroll
        for (int t = 0; t < 5; ++t)
            #pragma unroll
            for (int q = 0; q < 4; ++q) dacc[t][q] = 0.f;

        #pragma unroll
        for (int kh = 0; kh < 2; ++kh){
            #pragma unroll
            for (int t = 0; t < 5; ++t){
                const int T = 2*w + t;
                const uint4* pb = Bf + ((kh*13 + T)*4)*32 + lane;
                uint4 f0 = __ldg(pb);
                uint4 f1 = __ldg(pb + 32);
                uint4 f2 = __ldg(pb + 64);
                uint4 f3 = __ldg(pb + 96);
                const uint32_t* ab = &areg[kh*32];
                mma8(dacc[t], ab +  0, f0.x, f0.y);
                mma8(dacc[t], ab +  4, f0.z, f0.w);
                mma8(dacc[t], ab +  8, f1.x, f1.y);
                mma8(dacc[t], ab + 12, f1.z, f1.w);
                mma8(dacc[t], ab + 16, f2.x, f2.y);
                mma8(dacc[t], ab + 20, f2.z, f2.w);
                mma8(dacc[t], ab + 24, f3.x, f3.y);
                mma8(dacc[t], ab + 28, f3.z, f3.w);
            }
        }

        // band extraction into Dsm[dxi][m]
        #pragma unroll
        for (int t = 0; t < 5; ++t){
            const int dx0 = 8*t + 2*tig - grp;
            if ((unsigned)dx0 < 21u)     Dsm[dx0*80 + m0]     = dacc[t][0];
            if ((unsigned)(dx0+1) < 21u) Dsm[(dx0+1)*80 + m0] = dacc[t][1];
            const int dx2 = dx0 - 8;
            if ((unsigned)dx2 < 21u)     Dsm[dx2*80 + m0+8]     = dacc[t][2];
            if ((unsigned)(dx2+1) < 21u) Dsm[(dx2+1)*80 + m0+8] = dacc[t][3];
        }
        __syncthreads();

        // coalesced store of 21 x 80 band rows (160 threads)
        {
            const int mloc = (tid >= 80) ? tid - 80 : tid;
            const int dxi0 = (tid >= 80) ? 1 : 0;
            float* orow = g_raw + ((size_t)(b*441 + pane*21) * 158 + y) * 160
                          + p*80 + mloc;
            #pragma unroll
            for (int k = 0; k < 10; ++k){
                int dxi = 2*k + dxi0;
                orow[(size_t)dxi * CH_STRIDE] = Dsm[dxi*80 + mloc];
            }
            if (dxi0 == 0)
                orow[(size_t)20 * CH_STRIDE] = Dsm[20*80 + mloc];
        }
        __syncthreads();   // Dsm reads done before next pane's extraction writes
    }
}

// ---------------- Pass 2: 3x3 box sum / 1152 on parity-split rows ----------------
__global__ void corr_pass2(float* __restrict__ out){
    const int tid = threadIdx.x;            // 156
    const int qx = tid % 39;
    const int qy = blockIdx.y * 4 + tid / 39;
    const int ch = blockIdx.z;
    if (qy >= 39) return;
    const int i0 = qy * 4, j0 = qx * 4, m0 = qx * 2;
    const float inv = 1.0f / 1152.0f;

    const float* rb = g_raw + (size_t)ch * CH_STRIDE;
    float w6[6][4];
    #pragma unroll
    for (int rr = 0; rr < 6; ++rr){
        const float* row = rb + (size_t)(i0 + rr) * 160;
        float2 u = *(const float2*)(row + m0);
        float  u2 = row[m0 + 2];
        float2 v = *(const float2*)(row + 80 + m0);
        float  v2 = row[80 + m0 + 2];
        w6[rr][0] = u.x + v.x + u.y;
        w6[rr][1] = v.x + u.y + v.y;
        w6[rr][2] = u.y + v.y + u2;
        w6[rr][3] = v.y + u2 + v2;
    }
    float* ob = out + (size_t)ch * HO * WO + j0;
    #pragma unroll
    for (int i = 0; i < 4; ++i){
        float4 o;
        o.x = (w6[i][0] + w6[i+1][0] + w6[i+2][0]) * inv;
        o.y = (w6[i][1] + w6[i+1][1] + w6[i+2][1]) * inv;
        o.z = (w6[i][2] + w6[i+1][2] + w6[i+2][2]) * inv;
        o.w = (w6[i][3] + w6[i+1][3] + w6[i+2][3]) * inv;
        *reinterpret_cast<float4*>(ob + (size_t)(i0 + i) * WO) = o;
    }
}

extern "C" void kernel_launch(void* const* d_in, const int* in_sizes, int n_in,
                              void* d_out, int out_size){
    const float* in1 = (const float*)d_in[0];
    const float* in2 = (const float*)d_in[1];
    float* out = (float*)d_out;

    transAB<<<dim3(356, 4), 256>>>(in1, in2);

    cudaFuncSetAttribute(corr_mma,
                         cudaFuncAttributeMaxDynamicSharedMemorySize, SMEM_TOTAL);
    corr_mma<<<dim3(158, 2, 4), 160, SMEM_TOTAL>>>();

    dim3 g2(1, 10, 4*441), b2(156);
    corr_pass2<<<g2, b2>>>(out);
}

// round 16
// speedup vs baseline: 1.1870x; 1.1870x over previous
#include <cuda_runtime.h>
#include <cstdint>

#define HR 158
#define HO 156
#define WO 156
#define CH_STRIDE (158*160)

// smem map (bytes): B double-buffer (frag-ordered, ks2-packed) + band tile
#define SM_B0  0
#define BHALF  26624                 // 13 T x 4 ks2 x 32 lanes x 16B
#define SM_DS  (2*BHALF)             // 53248
#define SMEM_TOTAL (SM_DS + 21*80*4) // 59968  (x3 CTAs = 180 KB < 228 KB)

// At frag-ordered: [b][y 158][p 2] x [mt 5][ks 16][lane 32][4]  (10240 f/pane)
__device__ __align__(16) float g_At[(size_t)4*158*2*10240];
// Bt frag-ordered: [b][y2i 198][p 2] x [kh 2][T 13][ks2 4][lane 32][4] (13312 f/pane)
__device__ __align__(16) float g_Bt[(size_t)4*198*2*13312];
// raw, parity-split rows: [b*441+ch][y 158][p 2][m 80]  (~178 MB)
__device__ __align__(16) float g_raw[(size_t)4*441*158*160];

static __device__ __forceinline__ float to_tf32(float x){
    float r; asm("cvt.rna.tf32.f32 %0, %1;" : "=f"(r) : "f"(x)); return r;
}

// ---------------- Pass 0: fused transpose/pad into FRAGMENT-ORDER tiles ------
// grid.x: [0,158) -> A row y ; [158,356) -> B row y2i. grid.y = b.
__global__ __launch_bounds__(256) void transAB(const float* __restrict__ in1,
                                               const float* __restrict__ in2){
    __shared__ float sm[32*193];
    const int bx = blockIdx.x, b = blockIdx.y;
    const int tid = threadIdx.x;

    if (bx < 158){
        const int y = bx;
        float* outp = g_At + (size_t)((b*158 + y)*2) * 10240;
        for (int cc = 0; cc < 4; ++cc){
            const int c0 = cc*32;
            __syncthreads();
            for (int idx = tid; idx < 32*192; idx += 256){
                int cl = idx / 192, xx = idx - cl*192;
                sm[cl*193 + xx] = in1[(((size_t)b*128 + c0 + cl)*192 + (y+17))*192 + xx];
            }
            __syncthreads();
            // 1280 float4 frag words: v -> (pp, mt, ks_l, lane)
            #pragma unroll
            for (int it = 0; it < 5; ++it){
                int v = tid + it*256;
                int lane = v & 31;
                int q = v >> 5;            // 0..39
                int ks_l = q & 3; q >>= 2; // 0..9
                int mt = q % 5, pp = q / 5;
                int grp = lane >> 2, tig = lane & 3;
                int m = 16*mt + grp;
                int x = 2*m + pp + 17;
                int cl = ks_l*8 + tig;
                float4 o;
                o.x = to_tf32(sm[cl*193 + x]);
                o.z = to_tf32(sm[(cl+4)*193 + x]);
                if (m + 8 <= 78){
                    o.y = to_tf32(sm[cl*193 + x + 16]);
                    o.w = to_tf32(sm[(cl+4)*193 + x + 16]);
                } else { o.y = 0.f; o.w = 0.f; }
                int ks = cc*4 + ks_l;
                float* dst = outp + (size_t)pp*10240 + ((mt*16 + ks)*32 + lane)*4;
                *reinterpret_cast<float4*>(dst) = o;
            }
        }
    } else {
        const int y2i = bx - 158;
        const int y2 = y2i - 3;
        const bool rowok = (y2 >= 0 && y2 < 192);
        float* outp = g_Bt + (size_t)((b*198 + y2i)*2) * 13312;
        for (int cc = 0; cc < 4; ++cc){
            const int c0 = cc*32;
            __syncthreads();
            for (int idx = tid; idx < 32*192; idx += 256){
                int cl = idx / 192, xx = idx - cl*192;
                sm[cl*193 + xx] = rowok ?
                    in2[(((size_t)b*128 + c0 + cl)*192 + y2)*192 + xx] : 0.f;
            }
            __syncthreads();
            // 3328 float2 frag words: v -> (pp, T, ks_l, lane)
            const int kh = cc >> 1, kslc = (cc & 1)*4;
            #pragma unroll
            for (int it = 0; it < 13; ++it){
                int v = tid + it*256;
                int lane = v & 31;
                int q = v >> 5;            // 0..103
                int ks_l = q & 3; q >>= 2; // 0..25
                int T = q % 13, pp = q / 13;
                int grp = lane >> 2, tig = lane & 3;
                int n = T*8 + grp;
                int x = 2*n + pp - 3;
                int cl = ks_l*8 + tig;
                float2 o;
                o.x = ((unsigned)x < 192u) ? to_tf32(sm[cl*193 + x]) : 0.f;
                o.y = ((unsigned)x < 192u) ? to_tf32(sm[(cl+4)*193 + x]) : 0.f;
                int ksl = kslc + ks_l;
                // [kh][T][ks2][lane][4]: words 0-1 = ksl even, 2-3 = ksl odd
                float* dst = outp + (size_t)pp*13312 +
                             ((((kh*13 + T)*4 + (ksl >> 1))*32 + lane)*4 + (ksl & 1)*2);
                *reinterpret_cast<float2*>(dst) = o;
            }
        }
    }
}

// ---------------- helpers ----------------
__device__ __forceinline__ void cpa16(uint32_t dst, const void* src){
    asm volatile("cp.async.cg.shared.global [%0], [%1], 16;" :: "r"(dst), "l"(src));
}
__device__ __forceinline__ void mma8(float* d, const uint32_t* a, uint32_t b0, uint32_t b1){
    asm volatile(
        "mma.sync.aligned.m16n8k8.row.col.f32.tf32.tf32.f32 "
        "{%0,%1,%2,%3}, {%4,%5,%6,%7}, {%8,%9}, {%0,%1,%2,%3};"
        : "+f"(d[0]), "+f"(d[1]), "+f"(d[2]), "+f"(d[3])
        : "r"(a[0]), "r"(a[1]), "r"(a[2]), "r"(a[3]), "r"(b0), "r"(b1));
}

// ---------------- Pass 1: banded tf32 MMA, cp.async pipeline + LDS.128 ------
// grid (y 158, p 2, b 4); block 160 = 5 warps, warp w owns m-rows 16w..16w+15
// and n8-tiles T = 2w..2w+4. B pane in two 64-channel halves, double-buffered.
extern __shared__ __align__(16) char smem_dyn[];

__global__ __launch_bounds__(160, 3)
void corr_mma(){
    const int y = blockIdx.x, p = blockIdx.y, b = blockIdx.z;
    const int tid = threadIdx.x, w = tid >> 5, lane = tid & 31;
    const int grp = lane >> 2, tig = lane & 3;
    char* smc = smem_dyn;
    const uint32_t sb = (uint32_t)__cvta_generic_to_shared(smc);
    float* Dsm = (float*)(smc + SM_DS);

    const float* Ap = g_At + ((size_t)(b*158 + y)*2 + p) * 10240;
    const size_t bbase = ((size_t)b*198 + y)*2 + p;
    const int m0 = 16*w + grp;

    // prologue: B(pane0, kh0) cp.async as group 0 (linear 26624B copy)
    {
        const char* Bb = (const char*)(g_Bt + bbase * 13312);
        for (int idx = tid; idx < 1664; idx += 160)
            cpa16(sb + SM_B0 + idx*16, Bb + idx*16);
    }
    asm volatile("cp.async.commit_group;" ::: "memory");

    // A fragments: 16 coalesced LDG.128 per thread, once per block
    uint32_t areg[64];
    {
        const uint4* Af = (const uint4*)Ap;
        #pragma unroll
        for (int ks = 0; ks < 16; ++ks){
            uint4 f = __ldg(&Af[(w*16 + ks)*32 + lane]);
            areg[ks*4+0] = f.x; areg[ks*4+1] = f.y;
            areg[ks*4+2] = f.z; areg[ks*4+3] = f.w;
        }
    }

    for (int pane = 0; pane <= 20; ++pane){
        float dacc[5][4];
        #pragma unroll
        for (int t = 0; t < 5; ++t)
            #pragma unroll
            for (int q = 0; q < 4; ++q) dacc[t][q] = 0.f;

        #pragma unroll
        for (int kh = 0; kh < 2; ++kh){
            const int ph = pane*2 + kh;

            asm volatile("cp.async.wait_group 0;" ::: "memory");
            __syncthreads();

            if (ph < 41){
                const int npane = (ph+1) >> 1, nkh = (ph+1) & 1;
                const char* Bb = (const char*)(g_Bt +
                    (bbase + (size_t)npane*4) * 13312) + nkh*BHALF;
                const uint32_t dstb = sb + SM_B0 + ((ph+1) & 1) * BHALF;
                for (int idx = tid; idx < 1664; idx += 160)
                    cpa16(dstb + idx*16, Bb + idx*16);
                asm volatile("cp.async.commit_group;" ::: "memory");
            }

            const char* bufb = smc + SM_B0 + (ph & 1)*BHALF;
            const uint32_t* ab = &areg[kh*32];
            #pragma unroll
            for (int t = 0; t < 5; ++t){
                const int T = 2*w + t;
                const uint4* pb = (const uint4*)(bufb + ((T*4)*32 + lane)*16);
                uint4 f0 = pb[0];
                uint4 f1 = pb[32];
                uint4 f2 = pb[64];
                uint4 f3 = pb[96];
                mma8(dacc[t], ab +  0, f0.x, f0.y);
                mma8(dacc[t], ab +  4, f0.z, f0.w);
                mma8(dacc[t], ab +  8, f1.x, f1.y);
                mma8(dacc[t], ab + 12, f1.z, f1.w);
                mma8(dacc[t], ab + 16, f2.x, f2.y);
                mma8(dacc[t], ab + 20, f2.z, f2.w);
                mma8(dacc[t], ab + 24, f3.x, f3.y);
                mma8(dacc[t], ab + 28, f3.z, f3.w);
            }
            // no bottom sync: next phase's top sync orders buffer reuse
        }

        // band extraction into Dsm[dxi][m]
        #pragma unroll
        for (int t = 0; t < 5; ++t){
            const int dx0 = 8*t + 2*tig - grp;
            if ((unsigned)dx0 < 21u)     Dsm[dx0*80 + m0]     = dacc[t][0];
            if ((unsigned)(dx0+1) < 21u) Dsm[(dx0+1)*80 + m0] = dacc[t][1];
            const int dx2 = dx0 - 8;
            if ((unsigned)dx2 < 21u)     Dsm[dx2*80 + m0+8]     = dacc[t][2];
            if ((unsigned)(dx2+1) < 21u) Dsm[(dx2+1)*80 + m0+8] = dacc[t][3];
        }
        __syncthreads();

        // coalesced store of 21 x 80 band rows (160 threads)
        {
            const int mloc = (tid >= 80) ? tid - 80 : tid;
            const int dxi0 = (tid >= 80) ? 1 : 0;
            float* orow = g_raw + ((size_t)(b*441 + pane*21) * 158 + y) * 160
                          + p*80 + mloc;
            #pragma unroll
            for (int k = 0; k < 10; ++k){
                int dxi = 2*k + dxi0;
                orow[(size_t)dxi * CH_STRIDE] = Dsm[dxi*80 + mloc];
            }
            if (dxi0 == 0)
                orow[(size_t)20 * CH_STRIDE] = Dsm[20*80 + mloc];
        }
        // next pane's top sync orders these Dsm reads before rewrite
    }
}

// ---------------- Pass 2: 3x3 box sum / 1152 on parity-split rows ----------------
__global__ void corr_pass2(float* __restrict__ out){
    const int tid = threadIdx.x;            // 156
    const int qx = tid % 39;
    const int qy = blockIdx.y * 4 + tid / 39;
    const int ch = blockIdx.z;
    if (qy >= 39) return;
    const int i0 = qy * 4, j0 = qx * 4, m0 = qx * 2;
    const float inv = 1.0f / 1152.0f;

    const float* rb = g_raw + (size_t)ch * CH_STRIDE;
    float w6[6][4];
    #pragma unroll
    for (int rr = 0; rr < 6; ++rr){
        const float* row = rb + (size_t)(i0 + rr) * 160;
        float2 u = *(const float2*)(row + m0);
        float  u2 = row[m0 + 2];
        float2 v = *(const float2*)(row + 80 + m0);
        float  v2 = row[80 + m0 + 2];
        w6[rr][0] = u.x + v.x + u.y;
        w6[rr][1] = v.x + u.y + v.y;
        w6[rr][2] = u.y + v.y + u2;
        w6[rr][3] = v.y + u2 + v2;
    }
    float* ob = out + (size_t)ch * HO * WO + j0;
    #pragma unroll
    for (int i = 0; i < 4; ++i){
        float4 o;
        o.x = (w6[i][0] + w6[i+1][0] + w6[i+2][0]) * inv;
        o.y = (w6[i][1] + w6[i+1][1] + w6[i+2][1]) * inv;
        o.z = (w6[i][2] + w6[i+1][2] + w6[i+2][2]) * inv;
        o.w = (w6[i][3] + w6[i+1][3] + w6[i+2][3]) * inv;
        *reinterpret_cast<float4*>(ob + (size_t)(i0 + i) * WO) = o;
    }
}

extern "C" void kernel_launch(void* const* d_in, const int* in_sizes, int n_in,
                              void* d_out, int out_size){
    const float* in1 = (const float*)d_in[0];
    const float* in2 = (const float*)d_in[1];
    float* out = (float*)d_out;

    transAB<<<dim3(356, 4), 256>>>(in1, in2);

    cudaFuncSetAttribute(corr_mma,
                         cudaFuncAttributeMaxDynamicSharedMemorySize, SMEM_TOTAL);
    corr_mma<<<dim3(158, 2, 4), 160, SMEM_TOTAL>>>();

    dim3 g2(1, 10, 4*441), b2(156);
    corr_pass2<<<g2, b2>>>(out);
}

// round 17
// speedup vs baseline: 1.2131x; 1.0220x over previous
#include <cuda_runtime.h>
#include <cstdint>

#define HR 158
#define HO 156
#define WO 156
#define CH_STRIDE (158*160)

// smem map (bytes): B double-buffer (frag-ordered, ks2-packed) + band tile
#define SM_B0  0
#define BHALF  26624                 // 13 T x 4 ks2 x 32 lanes x 16B
#define SM_DS  (2*BHALF)             // 53248
#define SMEM_TOTAL (SM_DS + 21*80*4) // 59968  (x3 CTAs = 180 KB < 228 KB)

// At frag-ordered: [b][y 158][p 2] x [mt 5][ks 16][lane 32][4]  (10240 f/pane)
__device__ __align__(16) float g_At[(size_t)4*158*2*10240];
// Bt frag-ordered: [b][y2i 198][p 2] x [kh 2][T 13][ks2 4][lane 32][4] (13312 f/pane)
__device__ __align__(16) float g_Bt[(size_t)4*198*2*13312];
// raw, parity-split rows: [b*441+ch][y 158][p 2][m 80]  (~178 MB)
__device__ __align__(16) float g_raw[(size_t)4*441*158*160];

static __device__ __forceinline__ float to_tf32(float x){
    float r; asm("cvt.rna.tf32.f32 %0, %1;" : "=f"(r) : "f"(x)); return r;
}

// ---------------- Pass 0: fused transpose/pad into FRAGMENT-ORDER tiles ------
// grid.x: [0,158) -> A row y ; [158,356) -> B row y2i. grid.y = b.
// grid.z: channel-chunk half (cc = 2z, 2z+1) — halves per-block serial work.
__global__ __launch_bounds__(256) void transAB(const float* __restrict__ in1,
                                               const float* __restrict__ in2){
    __shared__ float sm[32*193];
    const int bx = blockIdx.x, b = blockIdx.y, z = blockIdx.z;
    const int tid = threadIdx.x;

    if (bx < 158){
        const int y = bx;
        float* outp = g_At + (size_t)((b*158 + y)*2) * 10240;
        for (int ci = 0; ci < 2; ++ci){
            const int cc = z*2 + ci;
            const int c0 = cc*32;
            __syncthreads();
            for (int idx = tid; idx < 32*192; idx += 256){
                int cl = idx / 192, xx = idx - cl*192;
                sm[cl*193 + xx] = in1[(((size_t)b*128 + c0 + cl)*192 + (y+17))*192 + xx];
            }
            __syncthreads();
            // 1280 float4 frag words: v -> (pp, mt, ks_l, lane)
            #pragma unroll
            for (int it = 0; it < 5; ++it){
                int v = tid + it*256;
                int lane = v & 31;
                int q = v >> 5;            // 0..39
                int ks_l = q & 3; q >>= 2; // 0..9
                int mt = q % 5, pp = q / 5;
                int grp = lane >> 2, tig = lane & 3;
                int m = 16*mt + grp;
                int x = 2*m + pp + 17;
                int cl = ks_l*8 + tig;
                float4 o;
                o.x = to_tf32(sm[cl*193 + x]);
                o.z = to_tf32(sm[(cl+4)*193 + x]);
                if (m + 8 <= 78){
                    o.y = to_tf32(sm[cl*193 + x + 16]);
                    o.w = to_tf32(sm[(cl+4)*193 + x + 16]);
                } else { o.y = 0.f; o.w = 0.f; }
                int ks = cc*4 + ks_l;
                float* dst = outp + (size_t)pp*10240 + ((mt*16 + ks)*32 + lane)*4;
                *reinterpret_cast<float4*>(dst) = o;
            }
        }
    } else {
        const int y2i = bx - 158;
        const int y2 = y2i - 3;
        const bool rowok = (y2 >= 0 && y2 < 192);
        float* outp = g_Bt + (size_t)((b*198 + y2i)*2) * 13312;
        for (int ci = 0; ci < 2; ++ci){
            const int cc = z*2 + ci;
            const int c0 = cc*32;
            __syncthreads();
            for (int idx = tid; idx < 32*192; idx += 256){
                int cl = idx / 192, xx = idx - cl*192;
                sm[cl*193 + xx] = rowok ?
                    in2[(((size_t)b*128 + c0 + cl)*192 + y2)*192 + xx] : 0.f;
            }
            __syncthreads();
            // 3328 float2 frag words: v -> (pp, T, ks_l, lane)
            const int kh = cc >> 1, kslc = (cc & 1)*4;
            #pragma unroll
            for (int it = 0; it < 13; ++it){
                int v = tid + it*256;
                int lane = v & 31;
                int q = v >> 5;            // 0..103
                int ks_l = q & 3; q >>= 2; // 0..25
                int T = q % 13, pp = q / 13;
                int grp = lane >> 2, tig = lane & 3;
                int n = T*8 + grp;
                int x = 2*n + pp - 3;
                int cl = ks_l*8 + tig;
                float2 o;
                o.x = ((unsigned)x < 192u) ? to_tf32(sm[cl*193 + x]) : 0.f;
                o.y = ((unsigned)x < 192u) ? to_tf32(sm[(cl+4)*193 + x]) : 0.f;
                int ksl = kslc + ks_l;
                // [kh][T][ks2][lane][4]: words 0-1 = ksl even, 2-3 = ksl odd
                float* dst = outp + (size_t)pp*13312 +
                             ((((kh*13 + T)*4 + (ksl >> 1))*32 + lane)*4 + (ksl & 1)*2);
                *reinterpret_cast<float2*>(dst) = o;
            }
        }
    }
}

// ---------------- helpers ----------------
__device__ __forceinline__ void cpa16(uint32_t dst, const void* src){
    asm volatile("cp.async.cg.shared.global [%0], [%1], 16;" :: "r"(dst), "l"(src));
}
__device__ __forceinline__ void mma8(float* d, const uint32_t* a, uint32_t b0, uint32_t b1){
    asm volatile(
        "mma.sync.aligned.m16n8k8.row.col.f32.tf32.tf32.f32 "
        "{%0,%1,%2,%3}, {%4,%5,%6,%7}, {%8,%9}, {%0,%1,%2,%3};"
        : "+f"(d[0]), "+f"(d[1]), "+f"(d[2]), "+f"(d[3])
        : "r"(a[0]), "r"(a[1]), "r"(a[2]), "r"(a[3]), "r"(b0), "r"(b1));
}

// ---------------- Pass 1: banded tf32 MMA, cp.async pipeline + LDS.128 ------
// grid (y 158, p 2, b 4); block 160 = 5 warps, warp w owns m-rows 16w..16w+15
// and n8-tiles T = 2w..2w+4. B pane in two 64-channel halves, double-buffered.
extern __shared__ __align__(16) char smem_dyn[];

__global__ __launch_bounds__(160, 3)
void corr_mma(){
    const int y = blockIdx.x, p = blockIdx.y, b = blockIdx.z;
    const int tid = threadIdx.x, w = tid >> 5, lane = tid & 31;
    const int grp = lane >> 2, tig = lane & 3;
    char* smc = smem_dyn;
    const uint32_t sb = (uint32_t)__cvta_generic_to_shared(smc);
    float* Dsm = (float*)(smc + SM_DS);

    const float* Ap = g_At + ((size_t)(b*158 + y)*2 + p) * 10240;
    const size_t bbase = ((size_t)b*198 + y)*2 + p;
    const int m0 = 16*w + grp;

    // prologue: B(pane0, kh0) cp.async as group 0 (linear 26624B copy)
    {
        const char* Bb = (const char*)(g_Bt + bbase * 13312);
        for (int idx = tid; idx < 1664; idx += 160)
            cpa16(sb + SM_B0 + idx*16, Bb + idx*16);
    }
    asm volatile("cp.async.commit_group;" ::: "memory");

    // A fragments: 16 coalesced LDG.128 per thread, once per block
    uint32_t areg[64];
    {
        const uint4* Af = (const uint4*)Ap;
        #pragma unroll
        for (int ks = 0; ks < 16; ++ks){
            uint4 f = __ldg(&Af[(w*16 + ks)*32 + lane]);
            areg[ks*4+0] = f.x; areg[ks*4+1] = f.y;
            areg[ks*4+2] = f.z; areg[ks*4+3] = f.w;
        }
    }

    for (int pane = 0; pane <= 20; ++pane){
        float dacc[5][4];
        #pragma unroll
        for (int t = 0; t < 5; ++t)
            #pragma unroll
            for (int q = 0; q < 4; ++q) dacc[t][q] = 0.f;

        #pragma unroll
        for (int kh = 0; kh < 2; ++kh){
            const int ph = pane*2 + kh;

            asm volatile("cp.async.wait_group 0;" ::: "memory");
            __syncthreads();

            if (ph < 41){
                const int npane = (ph+1) >> 1, nkh = (ph+1) & 1;
                const char* Bb = (const char*)(g_Bt +
                    (bbase + (size_t)npane*4) * 13312) + nkh*BHALF;
                const uint32_t dstb = sb + SM_B0 + ((ph+1) & 1) * BHALF;
                for (int idx = tid; idx < 1664; idx += 160)
                    cpa16(dstb + idx*16, Bb + idx*16);
                asm volatile("cp.async.commit_group;" ::: "memory");
            }

            const char* bufb = smc + SM_B0 + (ph & 1)*BHALF;
            const uint32_t* ab = &areg[kh*32];
            #pragma unroll
            for (int t = 0; t < 5; ++t){
                const int T = 2*w + t;
                const uint4* pb = (const uint4*)(bufb + ((T*4)*32 + lane)*16);
                uint4 f0 = pb[0];
                uint4 f1 = pb[32];
                uint4 f2 = pb[64];
                uint4 f3 = pb[96];
                mma8(dacc[t], ab +  0, f0.x, f0.y);
                mma8(dacc[t], ab +  4, f0.z, f0.w);
                mma8(dacc[t], ab +  8, f1.x, f1.y);
                mma8(dacc[t], ab + 12, f1.z, f1.w);
                mma8(dacc[t], ab + 16, f2.x, f2.y);
                mma8(dacc[t], ab + 20, f2.z, f2.w);
                mma8(dacc[t], ab + 24, f3.x, f3.y);
                mma8(dacc[t], ab + 28, f3.z, f3.w);
            }
            // no bottom sync: next phase's top sync orders buffer reuse
        }

        // band extraction into Dsm[dxi][m]
        #pragma unroll
        for (int t = 0; t < 5; ++t){
            const int dx0 = 8*t + 2*tig - grp;
            if ((unsigned)dx0 < 21u)     Dsm[dx0*80 + m0]     = dacc[t][0];
            if ((unsigned)(dx0+1) < 21u) Dsm[(dx0+1)*80 + m0] = dacc[t][1];
            const int dx2 = dx0 - 8;
            if ((unsigned)dx2 < 21u)     Dsm[dx2*80 + m0+8]     = dacc[t][2];
            if ((unsigned)(dx2+1) < 21u) Dsm[(dx2+1)*80 + m0+8] = dacc[t][3];
        }
        __syncthreads();

        // coalesced store of 21 x 80 band rows (160 threads)
        {
            const int mloc = (tid >= 80) ? tid - 80 : tid;
            const int dxi0 = (tid >= 80) ? 1 : 0;
            float* orow = g_raw + ((size_t)(b*441 + pane*21) * 158 + y) * 160
                          + p*80 + mloc;
            #pragma unroll
            for (int k = 0; k < 10; ++k){
                int dxi = 2*k + dxi0;
                orow[(size_t)dxi * CH_STRIDE] = Dsm[dxi*80 + mloc];
            }
            if (dxi0 == 0)
                orow[(size_t)20 * CH_STRIDE] = Dsm[20*80 + mloc];
        }
        // next pane's top sync orders these Dsm reads before rewrite
    }
}

// ---------------- Pass 2: 3x3 box sum / 1152 on parity-split rows ----------------
__global__ void corr_pass2(float* __restrict__ out){
    const int tid = threadIdx.x;            // 156
    const int qx = tid % 39;
    const int qy = blockIdx.y * 4 + tid / 39;
    const int ch = blockIdx.z;
    if (qy >= 39) return;
    const int i0 = qy * 4, j0 = qx * 4, m0 = qx * 2;
    const float inv = 1.0f / 1152.0f;

    const float* rb = g_raw + (size_t)ch * CH_STRIDE;
    float w6[6][4];
    #pragma unroll
    for (int rr = 0; rr < 6; ++rr){
        const float* row = rb + (size_t)(i0 + rr) * 160;
        float2 u = *(const float2*)(row + m0);
        float  u2 = row[m0 + 2];
        float2 v = *(const float2*)(row + 80 + m0);
        float  v2 = row[80 + m0 + 2];
        w6[rr][0] = u.x + v.x + u.y;
        w6[rr][1] = v.x + u.y + v.y;
        w6[rr][2] = u.y + v.y + u2;
        w6[rr][3] = v.y + u2 + v2;
    }
    float* ob = out + (size_t)ch * HO * WO + j0;
    #pragma unroll
    for (int i = 0; i < 4; ++i){
        float4 o;
        o.x = (w6[i][0] + w6[i+1][0] + w6[i+2][0]) * inv;
        o.y = (w6[i][1] + w6[i+1][1] + w6[i+2][1]) * inv;
        o.z = (w6[i][2] + w6[i+1][2] + w6[i+2][2]) * inv;
        o.w = (w6[i][3] + w6[i+1][3] + w6[i+2][3]) * inv;
        *reinterpret_cast<float4*>(ob + (size_t)(i0 + i) * WO) = o;
    }
}

extern "C" void kernel_launch(void* const* d_in, const int* in_sizes, int n_in,
                              void* d_out, int out_size){
    const float* in1 = (const float*)d_in[0];
    const float* in2 = (const float*)d_in[1];
    float* out = (float*)d_out;

    transAB<<<dim3(356, 4, 2), 256>>>(in1, in2);

    cudaFuncSetAttribute(corr_mma,
                         cudaFuncAttributeMaxDynamicSharedMemorySize, SMEM_TOTAL);
    corr_mma<<<dim3(158, 2, 4), 160, SMEM_TOTAL>>>();

    dim3 g2(1, 10, 4*441), b2(156);
    corr_pass2<<<g2, b2>>>(out);
}